// round 15
// baseline (speedup 1.0000x reference)
#include <cuda_runtime.h>
#include <math.h>

#define MAX_N     16
#define NBINS     4096
#define CAND_MAX  16384
#define HT        1024
#define BPB       37
#define FBB       18
#define TRIM_TILE 4096

__device__ unsigned int       g_hist[MAX_N * NBINS];
__device__ unsigned int       g_h16[MAX_N * 65536];   // digit counts -> cursors -> zero
__device__ int                g_count[MAX_N];
__device__ int                g_ctrim[MAX_N];
__device__ unsigned int       g_T24[MAX_N];
__device__ unsigned int       g_done1[MAX_N];
__device__ unsigned long long g_cand[MAX_N * CAND_MAX];
__device__ unsigned long long g_trim[MAX_N * CAND_MAX];   // digit-sorted (descending)

__device__ __forceinline__ unsigned int mono_f32(float f) {
    unsigned int u = __float_as_uint(f);
    return (u & 0x80000000u) ? ~u : (u | 0x80000000u);
}
__device__ __forceinline__ float inv_mono(unsigned int m) {
    unsigned int u = (m & 0x80000000u) ? (m & 0x7FFFFFFFu) : ~m;
    return __uint_as_float(u);
}

// Suffix-scan threshold over 4096-bin hist in sh[]. blockDim = 1024.
__device__ __forceinline__ void suffix_threshold(const unsigned int* sh,
                                                 unsigned int st,
                                                 unsigned int* warp_tot,
                                                 int* out, unsigned int* outAbove) {
    const int t = threadIdx.x, lane = t & 31, wid = t >> 5;
    unsigned int h0 = sh[t * 4], h1 = sh[t * 4 + 1], h2 = sh[t * 4 + 2], h3 = sh[t * 4 + 3];
    unsigned int seg = h0 + h1 + h2 + h3;
    unsigned int suf = seg;
#pragma unroll
    for (int d = 1; d < 32; d <<= 1) {
        unsigned int v = __shfl_down_sync(0xFFFFFFFFu, suf, d);
        if (lane + d < 32) suf += v;
    }
    if (lane == 0) warp_tot[wid] = suf;
    __syncthreads();
    if (wid == 0) {
        unsigned int wv = warp_tot[lane];
        unsigned int wsuf = wv;
#pragma unroll
        for (int d = 1; d < 32; d <<= 1) {
            unsigned int v = __shfl_down_sync(0xFFFFFFFFu, wsuf, d);
            if (lane + d < 32) wsuf += v;
        }
        warp_tot[lane] = wsuf - wv;
    }
    __syncthreads();
    unsigned int S  = suf + warp_tot[wid];
    unsigned int sN = S - seg;
    unsigned int s3 = sN + h3;
    unsigned int s2 = s3 + h2;
    unsigned int s1 = s2 + h1;
    unsigned int s0 = S;
    if      (s3 >= st && sN < st) { *out = t * 4 + 3; *outAbove = sN; }
    else if (s2 >= st && s3 < st) { *out = t * 4 + 2; *outAbove = s3; }
    else if (s1 >= st && s2 < st) { *out = t * 4 + 1; *outAbove = s2; }
    else if (s0 >= st && s1 < st) { *out = t * 4 + 0; *outAbove = s1; }
}

// ---------------------------------------------------------------------------
// K1: 24-bit sampled threshold (1 block/batch). Zeroes replay state.
// ---------------------------------------------------------------------------
__global__ void __launch_bounds__(1024) sample_thresh_kernel(
        const float* __restrict__ scores, int A, int k) {
    __shared__ unsigned int sh[NBINS];
    __shared__ unsigned int warp_tot[32];
    __shared__ int sT1, sT2;
    __shared__ unsigned int sS1, sDummy;
    const int b = blockIdx.x;
    const int t = threadIdx.x;

    for (int i = t; i < NBINS; i += 1024) { sh[i] = 0; g_hist[b * NBINS + i] = 0; }
    if (t == 0) g_count[b] = 0;
    __syncthreads();

    const size_t base = (size_t)b * (size_t)A;
    const int A4 = A >> 2;

    if ((A & 3) == 0 && A4 >= 4096) {
        const float4* s4 = (const float4*)(scores + base);
        unsigned int m[16];
#pragma unroll
        for (int r = 0; r < 4; r++) {
            int j = t + r * 1024;
            size_t pos = ((size_t)j * (size_t)A4) >> 12;
            float4 v = s4[pos];
            m[r * 4 + 0] = mono_f32(v.x);
            m[r * 4 + 1] = mono_f32(v.y);
            m[r * 4 + 2] = mono_f32(v.z);
            m[r * 4 + 3] = mono_f32(v.w);
        }
#pragma unroll
        for (int q = 0; q < 16; q++) atomicAdd(&sh[m[q] >> 20], 1u);
        __syncthreads();

        long long tgt = (16384LL * 7LL * (long long)k) / (4LL * (long long)A);  // ~3.5k
        if (tgt < 1) tgt = 1;
        if (tgt > 16384) tgt = 16384;
        const unsigned int st = (unsigned)tgt;

        suffix_threshold(sh, st, warp_tot, &sT1, &sS1);
        __syncthreads();
        const int T1 = sT1;
        const unsigned int S1 = sS1;
        __syncthreads();

        for (int i = t; i < NBINS; i += 1024) sh[i] = 0;
        __syncthreads();
#pragma unroll
        for (int q = 0; q < 16; q++)
            if ((int)(m[q] >> 20) == T1) atomicAdd(&sh[(m[q] >> 8) & 0xFFFu], 1u);
        __syncthreads();

        suffix_threshold(sh, st - S1, warp_tot, &sT2, &sDummy);
        __syncthreads();
        if (t == 0) g_T24[b] = ((unsigned)T1 << 12) | (unsigned)sT2;
    } else {
        for (int i = t; i < A; i += 1024)
            atomicAdd(&sh[mono_f32(scores[base + i]) >> 20], 1u);
        __syncthreads();
        suffix_threshold(sh, (unsigned)min(k, A), warp_tot, &sT1, &sS1);
        __syncthreads();
        if (t == 0) g_T24[b] = (unsigned)sT1 << 12;
    }
}

// ---------------------------------------------------------------------------
__device__ __forceinline__ void push_warp(int b, bool pred, unsigned long long key) {
    unsigned int bal = __ballot_sync(0xFFFFFFFFu, pred);
    if (!bal) return;
    const int lane = threadIdx.x & 31;
    const int leader = __ffs(bal) - 1;
    int base = 0;
    if (lane == leader) base = atomicAdd(&g_count[b], __popc(bal));
    base = __shfl_sync(0xFFFFFFFFu, base, leader);
    if (pred) {
        int pos = base + __popc(bal & ((1u << lane) - 1u));
        if (pos < CAND_MAX) g_cand[b * CAND_MAX + pos] = key;
        atomicAdd(&g_h16[((size_t)b << 16) + (unsigned)(key >> 48)], 1u);
    }
}

// ---------------------------------------------------------------------------
// K2: single full sweep — compact (m>>8) >= T24 + digit histogram.
// Fast path: one ballot on max-of-4; slow path only when the warp has a hit.
// grid (BPB, N) x HT
// ---------------------------------------------------------------------------
__global__ void __launch_bounds__(HT) compact_kernel(
        const float* __restrict__ scores, int A) {
    const int b = blockIdx.y;
    const unsigned int T24 = g_T24[b];
    const size_t base = (size_t)b * (size_t)A;
    const int lane = threadIdx.x & 31;

    if ((A & 3) == 0) {
        const float4* s4 = (const float4*)(scores + base);
        const int A4 = A >> 2;
        const int warp0 = blockIdx.x * (HT / 32) + (threadIdx.x >> 5);
        for (int i0 = warp0 * 32; i0 < A4; i0 += BPB * HT) {
            const int i = i0 + lane;
            const bool in = i < A4;
            float4 v;
            if (in) v = s4[i];
            unsigned int mx = in ? mono_f32(v.x) : 0u;
            unsigned int my = in ? mono_f32(v.y) : 0u;
            unsigned int mz = in ? mono_f32(v.z) : 0u;
            unsigned int mw = in ? mono_f32(v.w) : 0u;
            unsigned int mmax = max(max(mx, my), max(mz, mw));
            if (!__ballot_sync(0xFFFFFFFFu, (mmax >> 8) >= T24)) continue;
            unsigned int o = (unsigned)(i << 2);
            push_warp(b, (mx >> 8) >= T24,
                      ((unsigned long long)mx << 32) | (0xFFFFFFFFu - (o + 0u)));
            push_warp(b, (my >> 8) >= T24,
                      ((unsigned long long)my << 32) | (0xFFFFFFFFu - (o + 1u)));
            push_warp(b, (mz >> 8) >= T24,
                      ((unsigned long long)mz << 32) | (0xFFFFFFFFu - (o + 2u)));
            push_warp(b, (mw >> 8) >= T24,
                      ((unsigned long long)mw << 32) | (0xFFFFFFFFu - (o + 3u)));
        }
    } else {
        const int warp0 = blockIdx.x * (HT / 32) + (threadIdx.x >> 5);
        for (int i0 = warp0 * 32; i0 < A; i0 += BPB * HT) {
            const int i = i0 + lane;
            const bool in = i < A;
            unsigned int m = in ? mono_f32(scores[base + i]) : 0u;
            push_warp(b, in && (m >> 8) >= T24,
                      ((unsigned long long)m << 32) | (0xFFFFFFFFu - (unsigned)i));
        }
    }
}

// ---------------------------------------------------------------------------
// trim_finish: ONE 1024-thread block per batch.
// Walk the 64K digit histogram once to find d* (largest digit, suffix >= k)
// and the trim count; second walk turns h16 into scatter cursors (suffix
// offsets) for digits >= d* with h>0 and zeroes everything else; scatter
// candidates digit-sorted into g_trim; finally zero the used cursors.
// Leaves h16 entirely zero for the next replay.
// ---------------------------------------------------------------------------
__device__ void trim_finish(int b, int A, int k) {
    __shared__ unsigned int warp_tot[32];
    __shared__ unsigned int sDigit, sTrim;
    const int t = threadIdx.x, lane = t & 31, wid = t >> 5;
    unsigned int* h16 = &g_h16[(size_t)b << 16];
    const unsigned int st = (unsigned)min(k, A);

    // pass A: per-thread segment sum + block suffix scan
    unsigned int csum = 0;
    {
        const uint4* hv = (const uint4*)(h16 + t * 64);
#pragma unroll
        for (int q = 0; q < 16; q++) {
            uint4 v = hv[q];
            csum += v.x + v.y + v.z + v.w;
        }
    }
    unsigned int suf = csum;
#pragma unroll
    for (int d = 1; d < 32; d <<= 1) {
        unsigned int v = __shfl_down_sync(0xFFFFFFFFu, suf, d);
        if (lane + d < 32) suf += v;
    }
    if (lane == 0) warp_tot[wid] = suf;
    __syncthreads();
    if (wid == 0) {
        unsigned int wv = warp_tot[lane];
        unsigned int wsuf = wv;
#pragma unroll
        for (int d = 1; d < 32; d <<= 1) {
            unsigned int v = __shfl_down_sync(0xFFFFFFFFu, wsuf, d);
            if (lane + d < 32) wsuf += v;
        }
        warp_tot[lane] = wsuf - wv;
    }
    __syncthreads();
    const unsigned int accBase = (suf - csum) + warp_tot[wid];  // strictly above my 64 digits

    // walk my digits high->low to locate d*
    {
        unsigned int acc = accBase;
        const uint4* hv = (const uint4*)(h16 + t * 64);
        for (int q4 = 15; q4 >= 0; q4--) {
            uint4 v = hv[q4];
            unsigned int hw[4] = {v.x, v.y, v.z, v.w};
            for (int c = 3; c >= 0; c--) {
                unsigned int h = hw[c];
                if (acc < st && acc + h >= st) {
                    sDigit = (unsigned)(t * 64 + q4 * 4 + c);
                    sTrim  = acc + h;
                }
                acc += h;
            }
        }
    }
    __syncthreads();
    const unsigned int dstar = sDigit;
    const int trimCount = (int)min(sTrim, (unsigned)CAND_MAX);
    if (t == 0) g_ctrim[b] = trimCount;

    // pass B: cursors for digits >= d* (h>0), zero everything else
    {
        unsigned int acc = accBase;
        const uint4* hv = (const uint4*)(h16 + t * 64);
        unsigned int cur[64];
        for (int q4 = 15; q4 >= 0; q4--) {
            uint4 v = hv[q4];
            unsigned int hw[4] = {v.x, v.y, v.z, v.w};
            for (int c = 3; c >= 0; c--) {
                unsigned int dd = (unsigned)(t * 64 + q4 * 4 + c);
                unsigned int h = hw[c];
                cur[q4 * 4 + c] = (dd >= dstar && h > 0) ? acc : 0u;
                acc += h;
            }
        }
        __syncthreads();   // all reads of h16 done before overwrites
        uint4* hv_w = (uint4*)(h16 + t * 64);
#pragma unroll
        for (int q4 = 0; q4 < 16; q4++) {
            uint4 w;
            w.x = cur[q4 * 4 + 0]; w.y = cur[q4 * 4 + 1];
            w.z = cur[q4 * 4 + 2]; w.w = cur[q4 * 4 + 3];
            hv_w[q4] = w;
        }
    }
    __syncthreads();

    // scatter digit-sorted
    const int Ct = min(g_count[b], CAND_MAX);
    const unsigned long long* cand = &g_cand[(size_t)b * CAND_MAX];
    unsigned long long* trim = &g_trim[(size_t)b * CAND_MAX];
    for (int i = t; i < Ct; i += 1024) {
        unsigned long long key = cand[i];
        unsigned int dd = (unsigned)(key >> 48);
        if (dd >= dstar) {
            unsigned int pos = atomicAdd(&h16[dd], 1u);
            if (pos < (unsigned)CAND_MAX) trim[pos] = key;
        }
    }
    __syncthreads();

    // zero the used cursors (their digits are exactly the trimmed keys' digits)
    for (int i = t; i < trimCount; i += 1024)
        h16[(unsigned)(trim[i] >> 48)] = 0;
}

// ---------------------------------------------------------------------------
// K3: success path -> block 0 runs trim_finish. Fallback (~never): exact hist
// sweep; finisher re-thresholds, zeroes h16, recompacts alone, then trims.
// grid (FBB, N) x 1024
// ---------------------------------------------------------------------------
__global__ void __launch_bounds__(1024) fb_kernel(
        const float* __restrict__ scores, int A, int k) {
    const int b = blockIdx.y;
    const int t = threadIdx.x;
    unsigned int* h16 = &g_h16[(size_t)b << 16];

    {
        const int c = g_count[b];
        if (c >= min(k, A) && c <= CAND_MAX) {
            if (blockIdx.x != 0) return;
            trim_finish(b, A, k);
            return;
        }
    }
    __shared__ unsigned int sh[NBINS];
    __shared__ unsigned int warp_tot2[32];
    __shared__ int sT;
    __shared__ unsigned int sAb;
    __shared__ bool s_last;
    const size_t base = (size_t)b * (size_t)A;

    for (int i = t; i < NBINS; i += 1024) sh[i] = 0;
    __syncthreads();
    for (int i = blockIdx.x * 1024 + t; i < A; i += FBB * 1024)
        atomicAdd(&sh[mono_f32(scores[base + i]) >> 20], 1u);
    __syncthreads();
    for (int i = t; i < NBINS; i += 1024) {
        unsigned int c = sh[i];
        if (c) atomicAdd(&g_hist[b * NBINS + i], c);
    }
    __threadfence();
    __syncthreads();
    if (t == 0) s_last = (atomicAdd(&g_done1[b], 1u) == (unsigned)gridDim.x - 1u);
    __syncthreads();
    if (!s_last) return;
    if (t == 0) g_done1[b] = 0;

    for (int i = t; i < NBINS; i += 1024) sh[i] = g_hist[b * NBINS + i];
    __syncthreads();
    suffix_threshold(sh, (unsigned)min(k, A), warp_tot2, &sT, &sAb);
    __syncthreads();
    const unsigned int T24 = (unsigned)sT << 12;
    if (t == 0) { g_T24[b] = T24; g_count[b] = 0; }
    for (int i = t; i < 65536; i += 1024) h16[i] = 0;   // full reset (pathological)
    __syncthreads();

    for (int i = t; i < A; i += 1024) {
        unsigned int m = mono_f32(scores[base + i]);
        if ((m >> 8) >= T24) {
            unsigned long long key = ((unsigned long long)m << 32) |
                                     (unsigned long long)(0xFFFFFFFFu - (unsigned)i);
            int p = atomicAdd(&g_count[b], 1);
            if (p < CAND_MAX) g_cand[b * CAND_MAX + p] = key;
            atomicAdd(&h16[(unsigned)(key >> 48)], 1u);
        }
    }
    __syncthreads();
    trim_finish(b, A, k);
}

// ---------------------------------------------------------------------------
__device__ __forceinline__ void decode_one(unsigned long long key, int r,
                                           const float* __restrict__ anchors,
                                           const float* __restrict__ breg,
                                           float* __restrict__ out,
                                           size_t base, int b, int k) {
    const float CLIP = 4.135166556742356f;   // log(1000/16)
    unsigned int idx = 0xFFFFFFFFu - (unsigned int)(key & 0xFFFFFFFFull);
    float sc = inv_mono((unsigned int)(key >> 32));
    size_t g4 = (base + (size_t)idx) * 4;

    float4 box = *(const float4*)(anchors + g4);
    float4 rc  = *(const float4*)(breg + g4);

    float w  = box.z - box.x + 1.0f;
    float h  = box.w - box.y + 1.0f;
    float cx = box.x + 0.5f * w;
    float cy = box.y + 0.5f * h;

    float dw = fminf(rc.z, CLIP);
    float dh = fminf(rc.w, CLIP);

    float pcx = rc.x * w + cx;
    float pcy = rc.y * h + cy;
    float pw  = expf(dw) * w;
    float ph  = expf(dh) * h;

    float* o = out + ((size_t)b * k + r) * 5;
    o[0] = pcx - 0.5f * pw;
    o[1] = pcy - 0.5f * ph;
    o[2] = pcx + 0.5f * pw - 1.0f;
    o[3] = pcy + 0.5f * ph - 1.0f;
    o[4] = sc;
}

// ---------------------------------------------------------------------------
// K4: rank + decode over the digit-sorted trimmed set. rank = group_start +
// #greater within the digit group (binary-searched bounds). Warp-per-candidate.
// grid (8, N) x 512, 32 KB static smem.
// ---------------------------------------------------------------------------
__global__ void __launch_bounds__(512) rank_decode_kernel(
        const float* __restrict__ anchors,
        const float* __restrict__ breg,
        float* __restrict__ out,
        int A, int k) {
    __shared__ unsigned long long tile[TRIM_TILE];
    const int b = blockIdx.y;
    const int t = threadIdx.x;
    const int lane = t & 31;
    const int gw = blockIdx.x * (512 / 32) + (t >> 5);
    const int NW = gridDim.x * (512 / 32);
    const int Ctr = min(g_ctrim[b], CAND_MAX);
    const unsigned long long* trim = &g_trim[(size_t)b * CAND_MAX];
    const size_t base = (size_t)b * (size_t)A;

    const bool fits = (Ctr <= TRIM_TILE);
    if (fits) {
        for (int i = t; i < Ctr; i += 512) tile[i] = trim[i];
        __syncthreads();
    }
    const unsigned long long* keys = fits ? tile : trim;

    for (int c = gw; c < Ctr; c += NW) {
        const unsigned long long key = keys[c];
        const unsigned int d = (unsigned)(key >> 48);

        // group start: first index in [0, c] with digit <= d (== d)
        int lo = 0, hi = c;
        while (lo < hi) {
            int mid = (lo + hi) >> 1;
            if ((unsigned)(keys[mid] >> 48) > d) lo = mid + 1; else hi = mid;
        }
        const int gs = lo;
        // group end: first index in (c, Ctr] with digit < d
        lo = c + 1; hi = Ctr;
        while (lo < hi) {
            int mid = (lo + hi) >> 1;
            if ((unsigned)(keys[mid] >> 48) >= d) lo = mid + 1; else hi = mid;
        }
        const int ge = lo;

        int r = 0;
        for (int j = gs + lane; j < ge; j += 32) r += (keys[j] > key);
#pragma unroll
        for (int dlt = 16; dlt >= 1; dlt >>= 1)
            r += __shfl_down_sync(0xFFFFFFFFu, r, dlt);
        if (lane == 0) {
            r += gs;
            if (r < k) decode_one(key, r, anchors, breg, out, base, b, k);
        }
    }
}

// ---------------------------------------------------------------------------
extern "C" void kernel_launch(void* const* d_in, const int* in_sizes, int n_in,
                              void* d_out, int out_size) {
    const float* anchors    = (const float*)d_in[0];
    const float* objectness = (const float*)d_in[1];
    const float* breg       = (const float*)d_in[2];
    float* out = (float*)d_out;

    const int NA = in_sizes[1];
    const int k  = 2000;
    const int N  = out_size / (k * 5);
    const int A  = NA / N;

    sample_thresh_kernel<<<N, 1024>>>(objectness, A, k);
    compact_kernel<<<dim3(BPB, N), HT>>>(objectness, A);
    fb_kernel<<<dim3(FBB, N), 1024>>>(objectness, A, k);
    rank_decode_kernel<<<dim3(8, N), 512>>>(anchors, breg, out, A, k);
}

// round 16
// speedup vs baseline: 1.2053x; 1.2053x over previous
#include <cuda_runtime.h>
#include <math.h>

#define MAX_N     16
#define NBINS     4096
#define CAND_MAX  16384
#define HT        1024
#define BPB       18
#define TRIM_TILE 4096

__device__ unsigned int       g_hist[MAX_N * NBINS];
__device__ unsigned int       g_h16[MAX_N * 65536];   // digit counts -> cursors -> zero
__device__ int                g_count[MAX_N];
__device__ int                g_ctrim[MAX_N];
__device__ unsigned int       g_T24[MAX_N];
__device__ unsigned int       g_done1[MAX_N];
__device__ unsigned long long g_cand[MAX_N * CAND_MAX];
__device__ unsigned long long g_trim[MAX_N * CAND_MAX];   // digit-sorted (descending)

__device__ __forceinline__ unsigned int mono_f32(float f) {
    unsigned int u = __float_as_uint(f);
    return (u & 0x80000000u) ? ~u : (u | 0x80000000u);
}
__device__ __forceinline__ float inv_mono(unsigned int m) {
    unsigned int u = (m & 0x80000000u) ? (m & 0x7FFFFFFFu) : ~m;
    return __uint_as_float(u);
}

// Suffix-scan threshold over 4096-bin hist in sh[]. blockDim = 1024.
__device__ __forceinline__ void suffix_threshold(const unsigned int* sh,
                                                 unsigned int st,
                                                 unsigned int* warp_tot,
                                                 int* out, unsigned int* outAbove) {
    const int t = threadIdx.x, lane = t & 31, wid = t >> 5;
    unsigned int h0 = sh[t * 4], h1 = sh[t * 4 + 1], h2 = sh[t * 4 + 2], h3 = sh[t * 4 + 3];
    unsigned int seg = h0 + h1 + h2 + h3;
    unsigned int suf = seg;
#pragma unroll
    for (int d = 1; d < 32; d <<= 1) {
        unsigned int v = __shfl_down_sync(0xFFFFFFFFu, suf, d);
        if (lane + d < 32) suf += v;
    }
    if (lane == 0) warp_tot[wid] = suf;
    __syncthreads();
    if (wid == 0) {
        unsigned int wv = warp_tot[lane];
        unsigned int wsuf = wv;
#pragma unroll
        for (int d = 1; d < 32; d <<= 1) {
            unsigned int v = __shfl_down_sync(0xFFFFFFFFu, wsuf, d);
            if (lane + d < 32) wsuf += v;
        }
        warp_tot[lane] = wsuf - wv;
    }
    __syncthreads();
    unsigned int S  = suf + warp_tot[wid];
    unsigned int sN = S - seg;
    unsigned int s3 = sN + h3;
    unsigned int s2 = s3 + h2;
    unsigned int s1 = s2 + h1;
    unsigned int s0 = S;
    if      (s3 >= st && sN < st) { *out = t * 4 + 3; *outAbove = sN; }
    else if (s2 >= st && s3 < st) { *out = t * 4 + 2; *outAbove = s3; }
    else if (s1 >= st && s2 < st) { *out = t * 4 + 1; *outAbove = s2; }
    else if (s0 >= st && s1 < st) { *out = t * 4 + 0; *outAbove = s1; }
}

// ---------------------------------------------------------------------------
// K1: 24-bit sampled threshold (1 block/batch). Zeroes replay state.
// ---------------------------------------------------------------------------
__global__ void __launch_bounds__(1024) sample_thresh_kernel(
        const float* __restrict__ scores, int A, int k) {
    __shared__ unsigned int sh[NBINS];
    __shared__ unsigned int warp_tot[32];
    __shared__ int sT1, sT2;
    __shared__ unsigned int sS1, sDummy;
    const int b = blockIdx.x;
    const int t = threadIdx.x;

    for (int i = t; i < NBINS; i += 1024) { sh[i] = 0; g_hist[b * NBINS + i] = 0; }
    if (t == 0) g_count[b] = 0;
    __syncthreads();

    const size_t base = (size_t)b * (size_t)A;
    const int A4 = A >> 2;

    if ((A & 3) == 0 && A4 >= 4096) {
        const float4* s4 = (const float4*)(scores + base);
        unsigned int m[16];
#pragma unroll
        for (int r = 0; r < 4; r++) {
            int j = t + r * 1024;
            size_t pos = ((size_t)j * (size_t)A4) >> 12;
            float4 v = s4[pos];
            m[r * 4 + 0] = mono_f32(v.x);
            m[r * 4 + 1] = mono_f32(v.y);
            m[r * 4 + 2] = mono_f32(v.z);
            m[r * 4 + 3] = mono_f32(v.w);
        }
#pragma unroll
        for (int q = 0; q < 16; q++) atomicAdd(&sh[m[q] >> 20], 1u);
        __syncthreads();

        long long tgt = (16384LL * 7LL * (long long)k) / (4LL * (long long)A);  // ~3.5k
        if (tgt < 1) tgt = 1;
        if (tgt > 16384) tgt = 16384;
        const unsigned int st = (unsigned)tgt;

        suffix_threshold(sh, st, warp_tot, &sT1, &sS1);
        __syncthreads();
        const int T1 = sT1;
        const unsigned int S1 = sS1;
        __syncthreads();

        for (int i = t; i < NBINS; i += 1024) sh[i] = 0;
        __syncthreads();
#pragma unroll
        for (int q = 0; q < 16; q++)
            if ((int)(m[q] >> 20) == T1) atomicAdd(&sh[(m[q] >> 8) & 0xFFFu], 1u);
        __syncthreads();

        suffix_threshold(sh, st - S1, warp_tot, &sT2, &sDummy);
        __syncthreads();
        if (t == 0) g_T24[b] = ((unsigned)T1 << 12) | (unsigned)sT2;
    } else {
        for (int i = t; i < A; i += 1024)
            atomicAdd(&sh[mono_f32(scores[base + i]) >> 20], 1u);
        __syncthreads();
        suffix_threshold(sh, (unsigned)min(k, A), warp_tot, &sT1, &sS1);
        __syncthreads();
        if (t == 0) g_T24[b] = (unsigned)sT1 << 12;
    }
}

// ---------------------------------------------------------------------------
__device__ __forceinline__ void push_warp(int b, bool pred, unsigned long long key) {
    unsigned int bal = __ballot_sync(0xFFFFFFFFu, pred);
    if (!bal) return;
    const int lane = threadIdx.x & 31;
    const int leader = __ffs(bal) - 1;
    int base = 0;
    if (lane == leader) base = atomicAdd(&g_count[b], __popc(bal));
    base = __shfl_sync(0xFFFFFFFFu, base, leader);
    if (pred) {
        int pos = base + __popc(bal & ((1u << lane) - 1u));
        if (pos < CAND_MAX) g_cand[b * CAND_MAX + pos] = key;
        atomicAdd(&g_h16[((size_t)b << 16) + (unsigned)(key >> 48)], 1u);
    }
}

// ---------------------------------------------------------------------------
// K2: single full sweep — compact (m>>8) >= T24 + digit histogram.
// (exactly R14's proven form) grid (BPB, N) x HT
// ---------------------------------------------------------------------------
__global__ void __launch_bounds__(HT) compact_kernel(
        const float* __restrict__ scores, int A) {
    const int b = blockIdx.y;
    const unsigned int T24 = g_T24[b];
    const size_t base = (size_t)b * (size_t)A;
    const int lane = threadIdx.x & 31;

    if ((A & 3) == 0) {
        const float4* s4 = (const float4*)(scores + base);
        const int A4 = A >> 2;
        const int warp0 = blockIdx.x * (HT / 32) + (threadIdx.x >> 5);
        for (int i0 = warp0 * 32; i0 < A4; i0 += BPB * HT) {
            const int i = i0 + lane;
            const bool in = i < A4;
            float4 v;
            if (in) v = s4[i];
            unsigned int o = (unsigned)(i << 2);
            unsigned int mx = in ? mono_f32(v.x) : 0u;
            unsigned int my = in ? mono_f32(v.y) : 0u;
            unsigned int mz = in ? mono_f32(v.z) : 0u;
            unsigned int mw = in ? mono_f32(v.w) : 0u;
            push_warp(b, in && (mx >> 8) >= T24,
                      ((unsigned long long)mx << 32) | (0xFFFFFFFFu - (o + 0u)));
            push_warp(b, in && (my >> 8) >= T24,
                      ((unsigned long long)my << 32) | (0xFFFFFFFFu - (o + 1u)));
            push_warp(b, in && (mz >> 8) >= T24,
                      ((unsigned long long)mz << 32) | (0xFFFFFFFFu - (o + 2u)));
            push_warp(b, in && (mw >> 8) >= T24,
                      ((unsigned long long)mw << 32) | (0xFFFFFFFFu - (o + 3u)));
        }
    } else {
        const int warp0 = blockIdx.x * (HT / 32) + (threadIdx.x >> 5);
        for (int i0 = warp0 * 32; i0 < A; i0 += BPB * HT) {
            const int i = i0 + lane;
            const bool in = i < A;
            unsigned int m = in ? mono_f32(scores[base + i]) : 0u;
            push_warp(b, in && (m >> 8) >= T24,
                      ((unsigned long long)m << 32) | (0xFFFFFFFFu - (unsigned)i));
        }
    }
}

// ---------------------------------------------------------------------------
// trim_finish: ONE 1024-thread block per batch. Finds d* (largest digit with
// suffix >= k), converts h16 into scatter cursors for digits >= d*, scatters
// candidates digit-sorted (descending) into g_trim, zeroes used cursors.
// Leaves h16 entirely zero for the next replay.
// ---------------------------------------------------------------------------
__device__ void trim_finish(int b, int A, int k) {
    __shared__ unsigned int warp_tot[32];
    __shared__ unsigned int sDigit, sTrim;
    const int t = threadIdx.x, lane = t & 31, wid = t >> 5;
    unsigned int* h16 = &g_h16[(size_t)b << 16];
    const unsigned int st = (unsigned)min(k, A);

    unsigned int csum = 0;
    {
        const uint4* hv = (const uint4*)(h16 + t * 64);
#pragma unroll
        for (int q = 0; q < 16; q++) {
            uint4 v = hv[q];
            csum += v.x + v.y + v.z + v.w;
        }
    }
    unsigned int suf = csum;
#pragma unroll
    for (int d = 1; d < 32; d <<= 1) {
        unsigned int v = __shfl_down_sync(0xFFFFFFFFu, suf, d);
        if (lane + d < 32) suf += v;
    }
    if (lane == 0) warp_tot[wid] = suf;
    __syncthreads();
    if (wid == 0) {
        unsigned int wv = warp_tot[lane];
        unsigned int wsuf = wv;
#pragma unroll
        for (int d = 1; d < 32; d <<= 1) {
            unsigned int v = __shfl_down_sync(0xFFFFFFFFu, wsuf, d);
            if (lane + d < 32) wsuf += v;
        }
        warp_tot[lane] = wsuf - wv;
    }
    __syncthreads();
    const unsigned int accBase = (suf - csum) + warp_tot[wid];

    {
        unsigned int acc = accBase;
        const uint4* hv = (const uint4*)(h16 + t * 64);
        for (int q4 = 15; q4 >= 0; q4--) {
            uint4 v = hv[q4];
            unsigned int hw[4] = {v.x, v.y, v.z, v.w};
            for (int c = 3; c >= 0; c--) {
                unsigned int h = hw[c];
                if (acc < st && acc + h >= st) {
                    sDigit = (unsigned)(t * 64 + q4 * 4 + c);
                    sTrim  = acc + h;
                }
                acc += h;
            }
        }
    }
    __syncthreads();
    const unsigned int dstar = sDigit;
    const int trimCount = (int)min(sTrim, (unsigned)CAND_MAX);
    if (t == 0) g_ctrim[b] = trimCount;

    {
        unsigned int acc = accBase;
        const uint4* hv = (const uint4*)(h16 + t * 64);
        unsigned int cur[64];
        for (int q4 = 15; q4 >= 0; q4--) {
            uint4 v = hv[q4];
            unsigned int hw[4] = {v.x, v.y, v.z, v.w};
            for (int c = 3; c >= 0; c--) {
                unsigned int dd = (unsigned)(t * 64 + q4 * 4 + c);
                unsigned int h = hw[c];
                cur[q4 * 4 + c] = (dd >= dstar && h > 0) ? acc : 0u;
                acc += h;
            }
        }
        __syncthreads();
        uint4* hv_w = (uint4*)(h16 + t * 64);
#pragma unroll
        for (int q4 = 0; q4 < 16; q4++) {
            uint4 w;
            w.x = cur[q4 * 4 + 0]; w.y = cur[q4 * 4 + 1];
            w.z = cur[q4 * 4 + 2]; w.w = cur[q4 * 4 + 3];
            hv_w[q4] = w;
        }
    }
    __syncthreads();

    const int Ct = min(g_count[b], CAND_MAX);
    const unsigned long long* cand = &g_cand[(size_t)b * CAND_MAX];
    unsigned long long* trim = &g_trim[(size_t)b * CAND_MAX];
    for (int i = t; i < Ct; i += 1024) {
        unsigned long long key = cand[i];
        unsigned int dd = (unsigned)(key >> 48);
        if (dd >= dstar) {
            unsigned int pos = atomicAdd(&h16[dd], 1u);
            if (pos < (unsigned)CAND_MAX) trim[pos] = key;
        }
    }
    __syncthreads();

    for (int i = t; i < trimCount; i += 1024)
        h16[(unsigned)(trim[i] >> 48)] = 0;
}

// ---------------------------------------------------------------------------
// K3: success path -> block 0 runs trim_finish. Fallback (~never): exact hist
// sweep; finisher re-thresholds, zeroes h16, recompacts alone, then trims.
// grid (BPB, N) x 1024
// ---------------------------------------------------------------------------
__global__ void __launch_bounds__(1024) fb_kernel(
        const float* __restrict__ scores, int A, int k) {
    const int b = blockIdx.y;
    const int t = threadIdx.x;
    unsigned int* h16 = &g_h16[(size_t)b << 16];

    {
        const int c = g_count[b];
        if (c >= min(k, A) && c <= CAND_MAX) {
            if (blockIdx.x != 0) return;
            trim_finish(b, A, k);
            return;
        }
    }
    __shared__ unsigned int sh[NBINS];
    __shared__ unsigned int warp_tot2[32];
    __shared__ int sT;
    __shared__ unsigned int sAb;
    __shared__ bool s_last;
    const size_t base = (size_t)b * (size_t)A;

    for (int i = t; i < NBINS; i += 1024) sh[i] = 0;
    __syncthreads();
    for (int i = blockIdx.x * 1024 + t; i < A; i += BPB * 1024)
        atomicAdd(&sh[mono_f32(scores[base + i]) >> 20], 1u);
    __syncthreads();
    for (int i = t; i < NBINS; i += 1024) {
        unsigned int c = sh[i];
        if (c) atomicAdd(&g_hist[b * NBINS + i], c);
    }
    __threadfence();
    __syncthreads();
    if (t == 0) s_last = (atomicAdd(&g_done1[b], 1u) == (unsigned)gridDim.x - 1u);
    __syncthreads();
    if (!s_last) return;
    if (t == 0) g_done1[b] = 0;

    for (int i = t; i < NBINS; i += 1024) sh[i] = g_hist[b * NBINS + i];
    __syncthreads();
    suffix_threshold(sh, (unsigned)min(k, A), warp_tot2, &sT, &sAb);
    __syncthreads();
    const unsigned int T24 = (unsigned)sT << 12;
    if (t == 0) { g_T24[b] = T24; g_count[b] = 0; }
    for (int i = t; i < 65536; i += 1024) h16[i] = 0;
    __syncthreads();

    for (int i = t; i < A; i += 1024) {
        unsigned int m = mono_f32(scores[base + i]);
        if ((m >> 8) >= T24) {
            unsigned long long key = ((unsigned long long)m << 32) |
                                     (unsigned long long)(0xFFFFFFFFu - (unsigned)i);
            int p = atomicAdd(&g_count[b], 1);
            if (p < CAND_MAX) g_cand[b * CAND_MAX + p] = key;
            atomicAdd(&h16[(unsigned)(key >> 48)], 1u);
        }
    }
    __syncthreads();
    trim_finish(b, A, k);
}

// ---------------------------------------------------------------------------
__device__ __forceinline__ void decode_one(unsigned long long key, int r,
                                           const float* __restrict__ anchors,
                                           const float* __restrict__ breg,
                                           float* __restrict__ out,
                                           size_t base, int b, int k) {
    const float CLIP = 4.135166556742356f;   // log(1000/16)
    unsigned int idx = 0xFFFFFFFFu - (unsigned int)(key & 0xFFFFFFFFull);
    float sc = inv_mono((unsigned int)(key >> 32));
    size_t g4 = (base + (size_t)idx) * 4;

    float4 box = *(const float4*)(anchors + g4);
    float4 rc  = *(const float4*)(breg + g4);

    float w  = box.z - box.x + 1.0f;
    float h  = box.w - box.y + 1.0f;
    float cx = box.x + 0.5f * w;
    float cy = box.y + 0.5f * h;

    float dw = fminf(rc.z, CLIP);
    float dh = fminf(rc.w, CLIP);

    float pcx = rc.x * w + cx;
    float pcy = rc.y * h + cy;
    float pw  = expf(dw) * w;
    float ph  = expf(dh) * h;

    float* o = out + ((size_t)b * k + r) * 5;
    o[0] = pcx - 0.5f * pw;
    o[1] = pcy - 0.5f * ph;
    o[2] = pcx + 0.5f * pw - 1.0f;
    o[3] = pcy + 0.5f * ph - 1.0f;
    o[4] = sc;
}

// ---------------------------------------------------------------------------
// K4: rank + decode over the digit-sorted trimmed set. Group starts come from
// a parallel boundary max-scan (no binary search). Warp-per-candidate with
// early digit-break intra-group count. grid (16, N) x 512.
// ---------------------------------------------------------------------------
__global__ void __launch_bounds__(512) rank_decode_kernel(
        const float* __restrict__ anchors,
        const float* __restrict__ breg,
        float* __restrict__ out,
        int A, int k) {
    __shared__ unsigned long long tile[TRIM_TILE];
    __shared__ unsigned short gstart[TRIM_TILE];
    __shared__ unsigned int wmax[16];
    const int b = blockIdx.y;
    const int t = threadIdx.x;
    const int lane = t & 31, wid = t >> 5;
    const int gw = blockIdx.x * (512 / 32) + wid;
    const int NW = gridDim.x * (512 / 32);
    const int Ctr = min(g_ctrim[b], CAND_MAX);
    const unsigned long long* trim = &g_trim[(size_t)b * CAND_MAX];
    const size_t base = (size_t)b * (size_t)A;

    if (Ctr <= TRIM_TILE) {
        for (int i = t; i < Ctr; i += 512) tile[i] = trim[i];
        __syncthreads();

        // ---- boundary max-scan: gstart[i] = start index of i's digit group
        unsigned int loc[8];
        unsigned int run = 0;
        const int j0 = t * 8;
#pragma unroll
        for (int q = 0; q < 8; q++) {
            const int j = j0 + q;
            unsigned int m = 0;
            if (j < Ctr && j > 0 &&
                (unsigned)(tile[j] >> 48) != (unsigned)(tile[j - 1] >> 48))
                m = (unsigned)j;
            run = max(run, m);
            loc[q] = run;
        }
        // block-wide inclusive max-scan over per-thread maxima
        unsigned int incl = run;
#pragma unroll
        for (int d = 1; d < 32; d <<= 1) {
            unsigned int v = __shfl_up_sync(0xFFFFFFFFu, incl, d);
            if (lane >= d) incl = max(incl, v);
        }
        if (lane == 31) wmax[wid] = incl;
        __syncthreads();
        unsigned int carry = 0;
        for (int wq = 0; wq < wid; wq++) carry = max(carry, wmax[wq]);
        unsigned int excl = carry;
        {
            unsigned int prev = __shfl_up_sync(0xFFFFFFFFu, incl, 1);
            if (lane > 0) excl = max(carry, prev);
        }
#pragma unroll
        for (int q = 0; q < 8; q++) {
            const int j = j0 + q;
            if (j < Ctr) gstart[j] = (unsigned short)max(excl, loc[q]);
        }
        __syncthreads();

        // ---- warp-per-candidate: rank = gs + #{group keys > key}
        for (int c = gw; c < Ctr; c += NW) {
            const unsigned long long key = tile[c];
            const unsigned int d = (unsigned)(key >> 48);
            const int gs = gstart[c];
            int r = 0;
            for (int j = gs + lane; j < Ctr; j += 32) {
                unsigned long long kj = tile[j];
                if ((unsigned)(kj >> 48) != d) break;
                r += (kj > key);
            }
#pragma unroll
            for (int dlt = 16; dlt >= 1; dlt >>= 1)
                r += __shfl_down_sync(0xFFFFFFFFu, r, dlt);
            if (lane == 0) {
                r += gs;
                if (r < k) decode_one(key, r, anchors, breg, out, base, b, k);
            }
        }
    } else {
        // pathological fallback: full compare against global (exact, slow)
        for (int c = gw; c < Ctr; c += NW) {
            const unsigned long long key = trim[c];
            int r = 0;
            for (int j = lane; j < Ctr; j += 32) r += (trim[j] > key);
#pragma unroll
            for (int dlt = 16; dlt >= 1; dlt >>= 1)
                r += __shfl_down_sync(0xFFFFFFFFu, r, dlt);
            if (lane == 0 && r < k)
                decode_one(key, r, anchors, breg, out, base, b, k);
        }
    }
}

// ---------------------------------------------------------------------------
extern "C" void kernel_launch(void* const* d_in, const int* in_sizes, int n_in,
                              void* d_out, int out_size) {
    const float* anchors    = (const float*)d_in[0];
    const float* objectness = (const float*)d_in[1];
    const float* breg       = (const float*)d_in[2];
    float* out = (float*)d_out;

    const int NA = in_sizes[1];
    const int k  = 2000;
    const int N  = out_size / (k * 5);
    const int A  = NA / N;

    sample_thresh_kernel<<<N, 1024>>>(objectness, A, k);
    compact_kernel<<<dim3(BPB, N), HT>>>(objectness, A);
    fb_kernel<<<dim3(BPB, N), 1024>>>(objectness, A, k);
    rank_decode_kernel<<<dim3(16, N), 512>>>(anchors, breg, out, A, k);
}